// round 1
// baseline (speedup 1.0000x reference)
#include <cuda_runtime.h>

// OcrEmbedding: out[b,t,:] = sum_{s=0..3, id!=0} table[id[b,t,s], :]
// B=32, T=512, S=4, D=256, V=50000.
// Inputs (metadata order): d_in[0] = subtoken_ids (int32, B*T*S),
//                          d_in[1] = table (float32, V*D).
// Output: float32, B*T*D.

#define BT   (32 * 512)   // 16384 token rows
#define D4   64           // D/4 float4 per row
#define S    4

__global__ __launch_bounds__(256) void ocr_embed_kernel(
    const int* __restrict__ ids,          // [BT, S]
    const float4* __restrict__ table,     // [V, D4]
    float4* __restrict__ out)             // [BT, D4]
{
    int gid = blockIdx.x * blockDim.x + threadIdx.x;   // 0 .. BT*D4-1
    int row = gid >> 6;      // token index
    int q   = gid & 63;      // which float4 within D

    // 4 subtoken ids for this token (broadcast across the 64 threads of the row;
    // L1 serves the redundancy).
    const int* id4 = ids + row * S;
    int i0 = __ldg(id4 + 0);
    int i1 = __ldg(id4 + 1);
    int i2 = __ldg(id4 + 2);
    int i3 = __ldg(id4 + 3);

    float4 acc = make_float4(0.f, 0.f, 0.f, 0.f);

    if (i0 != 0) {
        float4 v = __ldg(&table[(size_t)i0 * D4 + q]);
        acc.x += v.x; acc.y += v.y; acc.z += v.z; acc.w += v.w;
    }
    if (i1 != 0) {
        float4 v = __ldg(&table[(size_t)i1 * D4 + q]);
        acc.x += v.x; acc.y += v.y; acc.z += v.z; acc.w += v.w;
    }
    if (i2 != 0) {
        float4 v = __ldg(&table[(size_t)i2 * D4 + q]);
        acc.x += v.x; acc.y += v.y; acc.z += v.z; acc.w += v.w;
    }
    if (i3 != 0) {
        float4 v = __ldg(&table[(size_t)i3 * D4 + q]);
        acc.x += v.x; acc.y += v.y; acc.z += v.z; acc.w += v.w;
    }

    out[(size_t)row * D4 + q] = acc;
}

extern "C" void kernel_launch(void* const* d_in, const int* in_sizes, int n_in,
                              void* d_out, int out_size)
{
    const int*    ids   = (const int*)d_in[0];
    const float4* table = (const float4*)d_in[1];
    float4*       out   = (float4*)d_out;

    const int total   = BT * D4;           // 1,048,576 threads
    const int threads = 256;
    const int blocks  = total / threads;   // 4096

    ocr_embed_kernel<<<blocks, threads>>>(ids, table, out);
}